// round 8
// baseline (speedup 1.0000x reference)
#include <cuda_runtime.h>
#include <cuda_bf16.h>
#include <cuda_fp16.h>
#include <cstdint>
#include <math.h>

#define N 4096
#define KDIM 1024
#define NN ((size_t)N*(size_t)N)
#define OT_EPS 1e-6f
#define RC (1.0f/4096.0f)
#define NB 128                   // persistent sinkhorn blocks (<= #SMs, all co-resident)

// ======================= PTX helpers (sm_80-level only: no tcgen05!) =======================
__device__ __forceinline__ uint32_t smem_to_u32(const void* smem_ptr) {
    uint32_t addr;
    asm("{ .reg .u64 tmp; cvta.to.shared.u64 tmp, %1; cvt.u32.u64 %0, tmp; }"
        : "=r"(addr) : "l"(smem_ptr));
    return addr;
}
__device__ __forceinline__ void cpasync16(uint32_t dst, const void* src) {
    asm volatile("cp.async.cg.shared.global [%0], [%1], 16;" :: "r"(dst), "l"(src));
}
#define CP_COMMIT() asm volatile("cp.async.commit_group;" ::: "memory")
#define CP_WAIT0()  asm volatile("cp.async.wait_group 0;" ::: "memory")
#define CP_WAIT1()  asm volatile("cp.async.wait_group 1;" ::: "memory")

__device__ __forceinline__ void ldsm4(uint32_t* r, uint32_t addr) {
    asm volatile("ldmatrix.sync.aligned.m8n8.x4.shared.b16 {%0,%1,%2,%3}, [%4];"
        : "=r"(r[0]), "=r"(r[1]), "=r"(r[2]), "=r"(r[3]) : "r"(addr));
}
__device__ __forceinline__ void mma16816(float* d, const uint32_t* a, uint32_t b0, uint32_t b1) {
    asm volatile(
        "mma.sync.aligned.m16n8k16.row.col.f32.bf16.bf16.f32 "
        "{%0,%1,%2,%3}, {%4,%5,%6,%7}, {%8,%9}, {%0,%1,%2,%3};"
        : "+f"(d[0]), "+f"(d[1]), "+f"(d[2]), "+f"(d[3])
        : "r"(a[0]), "r"(a[1]), "r"(a[2]), "r"(a[3]), "r"(b0), "r"(b1));
}

// monotonic uint encoding for float atomicMax
__device__ __forceinline__ unsigned fenc(float f) {
    unsigned u = __float_as_uint(f);
    return (u & 0x80000000u) ? ~u : (u | 0x80000000u);
}
__device__ __forceinline__ float fdec(unsigned u) {
    return (u & 0x80000000u) ? __uint_as_float(u & 0x7fffffffu) : __uint_as_float(~u);
}

// ======================= device scratch =======================
__device__ __half g_P0h[16777216];               // 32 MB: exp(M' - rowmax') in fp16
__device__ __nv_bfloat16 g_Abf[4096*3072];       // 24 MB: [A_hi | A_hi | A_lo]
__device__ __nv_bfloat16 g_Bbf[4096*3072];       // 24 MB: [B_hi | B_lo | B_hi]
__device__ float g_zbuf[2][N];
__device__ float g_w[N], g_s[N], g_sinv[N];
__device__ unsigned g_rowmax_u[N];
__device__ float g_sum, g_sumsq, g_mean, g_istd, g_psum, g_pdiag;
__device__ unsigned g_barcnt;
__device__ volatile unsigned g_bargen;

// DIY grid barrier: all NB blocks co-resident (1 block/SM).
__device__ __forceinline__ void gbar() {
    __syncthreads();
    if (threadIdx.x == 0) {
        __threadfence();
        unsigned arr = atomicAdd(&g_barcnt, 1u) + 1u;
        unsigned gen = (arr + NB - 1u) / NB;
        if (arr == gen * NB) {
            g_bargen = gen;
        } else {
            while (g_bargen < gen) { }
        }
    }
    __syncthreads();
}

// ======================= init (re-runs on every graph replay) =======================
__global__ void k_init() {
    int gid = blockIdx.x * 256 + threadIdx.x;
    if (gid == 0) {
        g_sum = 0.f; g_sumsq = 0.f; g_psum = 0.f; g_pdiag = 0.f;
        g_barcnt = 0u; g_bargen = 0u;
    }
    if (gid < N) {
        g_zbuf[0][gid] = 0.f; g_zbuf[1][gid] = 0.f;
        g_s[gid] = 0.f; g_rowmax_u[gid] = 0u;
    }
}

// ======================= fused rownorm + bf16-split conversion =======================
// A' K-slices: [hi, hi, lo] ; B' K-slices: [hi, lo, hi]
__global__ void k_prep(const float* __restrict__ ft, const float* __restrict__ fs) {
    int row = blockIdx.x;
    int t = threadIdx.x;
    bool isA = row < N;
    int r = isA ? row : row - N;
    const float* src = (isA ? ft : fs) + (size_t)r * KDIM;
    float4 v = ((const float4*)src)[t];
    float ss = v.x*v.x + v.y*v.y + v.z*v.z + v.w*v.w;
    __shared__ float red[256];
    red[t] = ss; __syncthreads();
    for (int o = 128; o; o >>= 1) { if (t < o) red[t] += red[t + o]; __syncthreads(); }
    float rinv = 1.0f / fmaxf(sqrtf(red[0]), 1e-12f);

    __nv_bfloat16* dst = (isA ? g_Abf : g_Bbf) + (size_t)r * 3072;
    float x0 = v.x * rinv, x1 = v.y * rinv, x2 = v.z * rinv, x3 = v.w * rinv;
    __nv_bfloat16 h0 = __float2bfloat16(x0), h1 = __float2bfloat16(x1);
    __nv_bfloat16 h2 = __float2bfloat16(x2), h3 = __float2bfloat16(x3);
    __nv_bfloat16 l0 = __float2bfloat16(x0 - __bfloat162float(h0));
    __nv_bfloat16 l1 = __float2bfloat16(x1 - __bfloat162float(h1));
    __nv_bfloat16 l2 = __float2bfloat16(x2 - __bfloat162float(h2));
    __nv_bfloat16 l3 = __float2bfloat16(x3 - __bfloat162float(h3));
    __nv_bfloat162 hh0, hh1, ll0, ll1;
    hh0.x = h0; hh0.y = h1; hh1.x = h2; hh1.y = h3;
    ll0.x = l0; ll0.y = l1; ll1.x = l2; ll1.y = l3;
    __nv_bfloat162* d2 = (__nv_bfloat162*)dst;
    int c2 = t * 2;
    d2[c2] = hh0; d2[c2 + 1] = hh1;                       // slice 0: hi
    if (isA) {
        d2[512 + c2] = hh0; d2[512 + c2 + 1] = hh1;       // slice 1: hi
        d2[1024 + c2] = ll0; d2[1024 + c2 + 1] = ll1;     // slice 2: lo
    } else {
        d2[512 + c2] = ll0; d2[512 + c2 + 1] = ll1;       // slice 1: lo
        d2[1024 + c2] = hh0; d2[1024 + c2 + 1] = hh1;     // slice 2: hi
    }
}

// ======================= mma.sync bf16 GEMM + fused stats, K=3072 =======================
// 128x256 CTA tile, 8 warps (2 M x 4 N), warp tile 64x64. K-chunk 64, 3-stage cp.async.
// Stage = A 16KB + B 32KB = 48KB; 3 stages = 144KB (1 CTA/SM).
#define G_NCH 48
#define G_STAGE 49152
#define GEMM_SMEM (3 * G_STAGE)

__global__ void __launch_bounds__(256) k_gemm_mma(float* __restrict__ Mout) {
    extern __shared__ char sm[];
    uint32_t smb = smem_to_u32(sm);
    int tid = threadIdx.x, wid = tid >> 5, lane = tid & 31;
    int bx = blockIdx.x, by = blockIdx.y;
    const char* Ag = (const char*)g_Abf + (size_t)by * 128 * 6144;
    const char* Bg = (const char*)g_Bbf + (size_t)bx * 256 * 6144;

    int r_  = tid >> 3;                       // 0..31
    int q16 = (tid & 7) * 16;
    int swc = q16 ^ ((r_ & 7) << 4);          // swizzled column byte offset

    // preload chunks 0 and 1 (separate commit groups)
#pragma unroll
    for (int pc = 0; pc < 2; pc++) {
        uint32_t dst = smb + pc * G_STAGE;
        size_t kb = (size_t)pc * 128;
#pragma unroll
        for (int l = 0; l < 4; l++) {         // A: 128 rows
            int row = r_ + l * 32;
            cpasync16(dst + row * 128 + swc, Ag + (size_t)row * 6144 + kb + q16);
        }
#pragma unroll
        for (int l = 0; l < 8; l++) {         // B: 256 rows
            int row = r_ + l * 32;
            cpasync16(dst + 16384 + row * 128 + swc, Bg + (size_t)row * 6144 + kb + q16);
        }
        CP_COMMIT();
    }

    int wm = wid & 1, wn = wid >> 1;
    int la15 = lane & 15, khalf = (lane >> 4) * 16;

    float acc[4][8][4];
#pragma unroll
    for (int ma = 0; ma < 4; ma++)
#pragma unroll
        for (int na = 0; na < 8; na++)
#pragma unroll
            for (int i = 0; i < 4; i++) acc[ma][na][i] = 0.f;

#pragma unroll 1
    for (int c = 0; c < G_NCH; c++) {
        if (c + 2 < G_NCH) { CP_WAIT1(); } else { CP_WAIT0(); }
        __syncthreads();
        if (c + 2 < G_NCH) {
            uint32_t dst = smb + ((c + 2) % 3) * G_STAGE;
            size_t kb = (size_t)(c + 2) * 128;
#pragma unroll
            for (int l = 0; l < 4; l++) {
                int row = r_ + l * 32;
                cpasync16(dst + row * 128 + swc, Ag + (size_t)row * 6144 + kb + q16);
            }
#pragma unroll
            for (int l = 0; l < 8; l++) {
                int row = r_ + l * 32;
                cpasync16(dst + 16384 + row * 128 + swc, Bg + (size_t)row * 6144 + kb + q16);
            }
            CP_COMMIT();
        }
        uint32_t base = smb + (c % 3) * G_STAGE;
#pragma unroll
        for (int k16 = 0; k16 < 4; k16++) {
            int cb = k16 * 32 + khalf;
            uint32_t a[4][4], b[4][4];
#pragma unroll
            for (int ma = 0; ma < 4; ma++) {
                int r = wm * 64 + ma * 16 + la15;
                ldsm4(a[ma], base + r * 128 + (cb ^ ((r & 7) << 4)));
            }
#pragma unroll
            for (int nb = 0; nb < 4; nb++) {
                int r = wn * 64 + nb * 16 + la15;
                ldsm4(b[nb], base + 16384 + r * 128 + (cb ^ ((r & 7) << 4)));
            }
#pragma unroll
            for (int ma = 0; ma < 4; ma++)
#pragma unroll
                for (int n8 = 0; n8 < 8; n8++)
                    mma16816(acc[ma][n8], a[ma], b[n8 >> 1][n8 & 1], b[n8 >> 1][(n8 & 1) + 2]);
        }
    }

    // ---- epilogue: scalar stores (Mout only 4B aligned) + fused stats ----
    int gid = lane >> 2, tig = lane & 3;
    float tsum = 0.f, tsq = 0.f;
#pragma unroll
    for (int ma = 0; ma < 4; ma++) {
        float rm0 = -1e30f, rm1 = -1e30f;
        int row = by * 128 + wm * 64 + ma * 16 + gid;
#pragma unroll
        for (int n8 = 0; n8 < 8; n8++) {
            int col = bx * 256 + wn * 64 + n8 * 8 + tig * 2;
            float a0 = acc[ma][n8][0], a1 = acc[ma][n8][1];
            float a2 = acc[ma][n8][2], a3 = acc[ma][n8][3];
            float* p0 = Mout + (size_t)row * 4096 + col;
            float* p1 = Mout + (size_t)(row + 8) * 4096 + col;
            p0[0] = a0; p0[1] = a1; p1[0] = a2; p1[1] = a3;
            tsum += (a0 + a1) + (a2 + a3);
            tsq  += a0*a0 + a1*a1 + a2*a2 + a3*a3;
            rm0 = fmaxf(rm0, fmaxf(a0, a1));
            rm1 = fmaxf(rm1, fmaxf(a2, a3));
        }
        rm0 = fmaxf(rm0, __shfl_xor_sync(0xffffffffu, rm0, 1));
        rm0 = fmaxf(rm0, __shfl_xor_sync(0xffffffffu, rm0, 2));
        rm1 = fmaxf(rm1, __shfl_xor_sync(0xffffffffu, rm1, 1));
        rm1 = fmaxf(rm1, __shfl_xor_sync(0xffffffffu, rm1, 2));
        if (tig == 0) {
            atomicMax(&g_rowmax_u[row], fenc(rm0));
            atomicMax(&g_rowmax_u[row + 8], fenc(rm1));
        }
    }
    __shared__ float rsum[256], rsq[256];
    rsum[tid] = tsum; rsq[tid] = tsq; __syncthreads();
    for (int o = 128; o; o >>= 1) {
        if (tid < o) { rsum[tid] += rsum[tid + o]; rsq[tid] += rsq[tid + o]; }
        __syncthreads();
    }
    if (tid == 0) { atomicAdd(&g_sum, rsum[0]); atomicAdd(&g_sumsq, rsq[0]); }
}

__global__ void k_stats2() {
    double s = (double)g_sum, s2 = (double)g_sumsq;
    double n = (double)NN;
    double mean = s / n;
    double var = (s2 - n * mean * mean) / (n - 1.0);   // ddof=1
    g_mean = (float)mean;
    g_istd = (float)(1.0 / sqrt(var));
}

// ======================= standardize M in place, build fp16 P0 =======================
__global__ void k_makeP0(float* __restrict__ Mio) {
    int i = blockIdx.x, t = threadIdx.x;
    float mean = g_mean, istd = g_istd;
    float rmax = fdec(g_rowmax_u[i]);
    float* mrow = Mio + (size_t)i * N;
    __half2* prow = (__half2*)(g_P0h + (size_t)i * N);
#pragma unroll
    for (int k = 0; k < 8; k++) {
        int jp = t + 256 * k;                // pair index
        float m0 = mrow[2*jp], m1 = mrow[2*jp + 1];
        mrow[2*jp]     = (m0 - mean) * istd;
        mrow[2*jp + 1] = (m1 - mean) * istd;
        float e0 = __expf((m0 - rmax) * istd);
        float e1 = __expf((m1 - rmax) * istd);
        prow[jp] = __floats2half2_rn(e0, e1);
    }
}

// ======================= persistent fused Sinkhorn (all 20 iters + final + sinv) =========
__global__ void __launch_bounds__(256) k_sinkall() {
    extern __shared__ char smraw[];
    float* v_sm = (float*)smraw;                           // 4096 floats  (16 KB)
    __half2* smrows = (__half2*)(smraw + 16384);           // 8 rows x 2048 half2 (64 KB)
    __shared__ float su[8];
    __shared__ float red[256];
    int t = threadIdx.x, w = t >> 5, lane = t & 31;

    for (int j = t; j < N; j += 256) v_sm[j] = 1.0f;
    __syncthreads();

    const float2* v2 = (const float2*)v_sm;
    int done = 0, p = 0;

    for (int it = 0; it < 20 && !done; it++) {
        float za[16];
#pragma unroll
        for (int q = 0; q < 16; q++) za[q] = 0.f;

        for (int st = blockIdx.x; st < 512; st += NB) {
            int i0 = st * 8;
            {   // row pass: warp w -> row i0+w; stage row in smem, dot with v
                const __half2* row = (const __half2*)(g_P0h + (size_t)(i0 + w) * N);
                __half2* srow = smrows + (size_t)w * 2048;
                float acc = 0.f;
#pragma unroll 8
                for (int q = lane; q < 2048; q += 32) {
                    __half2 h = row[q];
                    srow[q] = h;
                    float2 f = __half22float2(h);
                    float2 vv = v2[q];
                    acc += f.x * vv.x + f.y * vv.y;
                }
#pragma unroll
                for (int o = 16; o; o >>= 1) acc += __shfl_down_sync(0xffffffffu, acc, o);
                if (lane == 0) su[w] = RC / acc;
            }
            __syncthreads();
#pragma unroll
            for (int kk = 0; kk < 8; kk++) {
                int j2 = t + kk * 256;
#pragma unroll
                for (int r = 0; r < 8; r++) {
                    float2 f = __half22float2(smrows[(size_t)r * 2048 + j2]);
                    float ur = su[r];
                    za[kk*2]     += f.x * ur;
                    za[kk*2 + 1] += f.y * ur;
                }
            }
            __syncthreads();
        }
        float* zb = g_zbuf[p];
#pragma unroll
        for (int kk = 0; kk < 8; kk++) {
            int j = (t + kk * 256) * 2;
            atomicAdd(&zb[j], za[kk*2]);
            atomicAdd(&zb[j + 1], za[kk*2 + 1]);
        }
        gbar();
        // phase 2: convergence check + v update (redundant in all blocks) + zero other buf
        float md = 0.f;
        float znew[16];
#pragma unroll
        for (int kk = 0; kk < 16; kk++) {
            int j = t + kk * 256;
            float zj = __ldcg(&g_zbuf[p][j]);
            znew[kk] = zj;
            md = fmaxf(md, fabsf(v_sm[j] * zj - RC));
        }
        red[t] = md; __syncthreads();
        for (int o = 128; o; o >>= 1) {
            if (t < o) red[t] = fmaxf(red[t], red[t + o]);
            __syncthreads();
        }
        md = red[0];
        int newdone = done | (md <= OT_EPS);
        if (!newdone) {
#pragma unroll
            for (int kk = 0; kk < 16; kk++) {
                int j = t + kk * 256;
                v_sm[j] = RC / znew[kk];
            }
        }
        done = newdone;
        if (t < 32) __stcg(&g_zbuf[p ^ 1][blockIdx.x * 32 + t], 0.f);
        gbar();
        p ^= 1;
    }

    // final pass: w_i = 1/(P0 v)_i ; s = P0^T w
    float sa[16];
#pragma unroll
    for (int q = 0; q < 16; q++) sa[q] = 0.f;
    for (int st = blockIdx.x; st < 512; st += NB) {
        int i0 = st * 8;
        {
            const __half2* row = (const __half2*)(g_P0h + (size_t)(i0 + w) * N);
            __half2* srow = smrows + (size_t)w * 2048;
            float acc = 0.f;
#pragma unroll 8
            for (int q = lane; q < 2048; q += 32) {
                __half2 h = row[q];
                srow[q] = h;
                float2 f = __half22float2(h);
                float2 vv = v2[q];
                acc += f.x * vv.x + f.y * vv.y;
            }
#pragma unroll
            for (int o = 16; o; o >>= 1) acc += __shfl_down_sync(0xffffffffu, acc, o);
            if (lane == 0) { float uu = 1.0f / acc; su[w] = uu; g_w[i0 + w] = uu; }
        }
        __syncthreads();
#pragma unroll
        for (int kk = 0; kk < 8; kk++) {
            int j2 = t + kk * 256;
#pragma unroll
            for (int r = 0; r < 8; r++) {
                float2 f = __half22float2(smrows[(size_t)r * 2048 + j2]);
                float ur = su[r];
                sa[kk*2]     += f.x * ur;
                sa[kk*2 + 1] += f.y * ur;
            }
        }
        __syncthreads();
    }
#pragma unroll
    for (int kk = 0; kk < 8; kk++) {
        int j = (t + kk * 256) * 2;
        atomicAdd(&g_s[j], sa[kk*2]);
        atomicAdd(&g_s[j + 1], sa[kk*2 + 1]);
    }
    gbar();
    // sinv tail: block b handles 32 entries
    if (t < 32) {
        int j = blockIdx.x * 32 + t;
        g_sinv[j] = 1.0f / __ldcg(&g_s[j]);
    }
}

// ======================= final P = w_i * P0_ij * sinv_j ; loss partials =======================
__global__ void k_final(float* __restrict__ Pout) {
    int i = blockIdx.x, t = threadIdx.x;
    float wi = g_w[i];
    const __half2* row = (const __half2*)(g_P0h + (size_t)i * N);
    const float2* sv2 = (const float2*)g_sinv;
    float ss = 0.f;
#pragma unroll
    for (int k = 0; k < 8; k++) {
        int jp = t + 256 * k;
        float2 f = __half22float2(row[jp]);
        float2 si = sv2[jp];
        float o0 = wi * f.x * si.x;
        float o1 = wi * f.y * si.y;
        size_t base = (size_t)i * N + (size_t)jp * 2;
        Pout[base] = o0; Pout[base + 1] = o1;
        ss += o0*o0 + o1*o1;
        int j = jp * 2;
        if (i == j) atomicAdd(&g_pdiag, o0);
        else if (i == j + 1) atomicAdd(&g_pdiag, o1);
    }
    __shared__ float red[256];
    red[t] = ss; __syncthreads();
    for (int o = 128; o; o >>= 1) { if (t < o) red[t] += red[t + o]; __syncthreads(); }
    if (t == 0) atomicAdd(&g_psum, red[0]);
}

__global__ void k_loss(float* __restrict__ out) {
    out[0] = sqrtf(g_psum - 2.0f * g_pdiag + (float)N);
}

// ======================= launch =======================
extern "C" void kernel_launch(void* const* d_in, const int* in_sizes, int n_in,
                              void* d_out, int out_size) {
    const float* ft = (const float*)d_in[0];
    const float* fs = (const float*)d_in[1];
    float* out  = (float*)d_out;
    float* Pout = out + 1;
    float* Mout = out + 1 + NN;

    cudaFuncSetAttribute(k_gemm_mma, cudaFuncAttributeMaxDynamicSharedMemorySize, GEMM_SMEM);
    cudaFuncSetAttribute(k_sinkall,  cudaFuncAttributeMaxDynamicSharedMemorySize, 81920);

    k_init<<<16, 256>>>();
    k_prep<<<2 * N, 256>>>(ft, fs);
    k_gemm_mma<<<dim3(16, 32), 256, GEMM_SMEM>>>(Mout);
    k_stats2<<<1, 1>>>();
    k_makeP0<<<N, 256>>>(Mout);
    k_sinkall<<<NB, 256, 81920>>>();
    k_final<<<N, 256>>>(Pout);
    k_loss<<<1, 1>>>(out);
}

// round 9
// speedup vs baseline: 1.1174x; 1.1174x over previous
#include <cuda_runtime.h>
#include <cuda_bf16.h>
#include <cuda_fp16.h>
#include <cstdint>
#include <math.h>

#define N 4096
#define KDIM 1024
#define NN ((size_t)N*(size_t)N)
#define OT_EPS 1e-6f
#define RC (1.0f/4096.0f)
#define NB 128                   // persistent sinkhorn blocks (<= #SMs, all co-resident)

// ======================= PTX helpers (sm_80-level only: no tcgen05!) =======================
__device__ __forceinline__ uint32_t smem_to_u32(const void* smem_ptr) {
    uint32_t addr;
    asm("{ .reg .u64 tmp; cvta.to.shared.u64 tmp, %1; cvt.u32.u64 %0, tmp; }"
        : "=r"(addr) : "l"(smem_ptr));
    return addr;
}
__device__ __forceinline__ void cpasync16(uint32_t dst, const void* src) {
    asm volatile("cp.async.cg.shared.global [%0], [%1], 16;" :: "r"(dst), "l"(src));
}
#define CP_COMMIT() asm volatile("cp.async.commit_group;" ::: "memory")
#define CP_WAIT0()  asm volatile("cp.async.wait_group 0;" ::: "memory")

__device__ __forceinline__ void ldsm4(uint32_t* r, uint32_t addr) {
    asm volatile("ldmatrix.sync.aligned.m8n8.x4.shared.b16 {%0,%1,%2,%3}, [%4];"
        : "=r"(r[0]), "=r"(r[1]), "=r"(r[2]), "=r"(r[3]) : "r"(addr));
}
__device__ __forceinline__ void mma16816(float* d, const uint32_t* a, uint32_t b0, uint32_t b1) {
    asm volatile(
        "mma.sync.aligned.m16n8k16.row.col.f32.bf16.bf16.f32 "
        "{%0,%1,%2,%3}, {%4,%5,%6,%7}, {%8,%9}, {%0,%1,%2,%3};"
        : "+f"(d[0]), "+f"(d[1]), "+f"(d[2]), "+f"(d[3])
        : "r"(a[0]), "r"(a[1]), "r"(a[2]), "r"(a[3]), "r"(b0), "r"(b1));
}

// monotonic uint encoding for float atomicMax
__device__ __forceinline__ unsigned fenc(float f) {
    unsigned u = __float_as_uint(f);
    return (u & 0x80000000u) ? ~u : (u | 0x80000000u);
}
__device__ __forceinline__ float fdec(unsigned u) {
    return (u & 0x80000000u) ? __uint_as_float(u & 0x7fffffffu) : __uint_as_float(~u);
}

// ======================= device scratch =======================
__device__ __half g_P0h[16777216];               // 32 MB: exp(M' - rowmax') in fp16
__device__ __nv_bfloat16 g_Abf[4096*3072];       // 24 MB: [A_hi | A_hi | A_lo]
__device__ __nv_bfloat16 g_Bbf[4096*3072];       // 24 MB: [B_hi | B_lo | B_hi]
__device__ float g_zit[21][N];                   // per-iteration z accumulators (pre-zeroed)
__device__ float g_w[N], g_s[N], g_sinv[N];
__device__ unsigned g_rowmax_u[N];
__device__ float g_sum, g_sumsq, g_psum, g_pdiag;
__device__ unsigned g_barcnt;
__device__ volatile unsigned g_bargen;

// DIY grid barrier: all NB blocks co-resident (1 block/SM).
__device__ __forceinline__ void gbar() {
    __syncthreads();
    if (threadIdx.x == 0) {
        __threadfence();
        unsigned arr = atomicAdd(&g_barcnt, 1u) + 1u;
        unsigned gen = (arr + NB - 1u) / NB;
        if (arr == gen * NB) {
            g_bargen = gen;
        } else {
            while (g_bargen < gen) { }
        }
    }
    __syncthreads();
}

// ======================= init (re-runs on every graph replay) =======================
__global__ void k_init() {
    int gid = blockIdx.x * 256 + threadIdx.x;           // 32768 threads
    if (gid == 0) {
        g_sum = 0.f; g_sumsq = 0.f; g_psum = 0.f; g_pdiag = 0.f;
        g_barcnt = 0u; g_bargen = 0u;
    }
    float* zflat = &g_zit[0][0];
    for (int j = gid; j < 21 * N; j += 32768) zflat[j] = 0.f;
    if (gid < N) { g_s[gid] = 0.f; g_rowmax_u[gid] = 0u; }
}

// ======================= fused rownorm + bf16-split conversion =======================
// A' K-slices: [hi, hi, lo] ; B' K-slices: [hi, lo, hi]
// A'.B'^T over K=3072 = ah*bh + ah*bl + al*bh  (drops only the ~2^-18 al*bl term)
__global__ void k_prep(const float* __restrict__ ft, const float* __restrict__ fs) {
    int row = blockIdx.x;
    int t = threadIdx.x;
    bool isA = row < N;
    int r = isA ? row : row - N;
    const float* src = (isA ? ft : fs) + (size_t)r * KDIM;
    float4 v = ((const float4*)src)[t];
    float ss = v.x*v.x + v.y*v.y + v.z*v.z + v.w*v.w;
    __shared__ float red[256];
    red[t] = ss; __syncthreads();
    for (int o = 128; o; o >>= 1) { if (t < o) red[t] += red[t + o]; __syncthreads(); }
    float rinv = 1.0f / fmaxf(sqrtf(red[0]), 1e-12f);

    __nv_bfloat16* dst = (isA ? g_Abf : g_Bbf) + (size_t)r * 3072;
    float x0 = v.x * rinv, x1 = v.y * rinv, x2 = v.z * rinv, x3 = v.w * rinv;
    __nv_bfloat16 h0 = __float2bfloat16(x0), h1 = __float2bfloat16(x1);
    __nv_bfloat16 h2 = __float2bfloat16(x2), h3 = __float2bfloat16(x3);
    __nv_bfloat16 l0 = __float2bfloat16(x0 - __bfloat162float(h0));
    __nv_bfloat16 l1 = __float2bfloat16(x1 - __bfloat162float(h1));
    __nv_bfloat16 l2 = __float2bfloat16(x2 - __bfloat162float(h2));
    __nv_bfloat16 l3 = __float2bfloat16(x3 - __bfloat162float(h3));
    __nv_bfloat162 hh0, hh1, ll0, ll1;
    hh0.x = h0; hh0.y = h1; hh1.x = h2; hh1.y = h3;
    ll0.x = l0; ll0.y = l1; ll1.x = l2; ll1.y = l3;
    __nv_bfloat162* d2 = (__nv_bfloat162*)dst;
    int c2 = t * 2;
    d2[c2] = hh0; d2[c2 + 1] = hh1;                       // slice 0: hi
    if (isA) {
        d2[512 + c2] = hh0; d2[512 + c2 + 1] = hh1;       // slice 1: hi
        d2[1024 + c2] = ll0; d2[1024 + c2 + 1] = ll1;     // slice 2: lo
    } else {
        d2[512 + c2] = ll0; d2[512 + c2 + 1] = ll1;       // slice 1: lo
        d2[1024 + c2] = hh0; d2[1024 + c2 + 1] = hh1;     // slice 2: hi
    }
}

// ======================= mma.sync bf16 GEMM + fused stats, K=3072 =======================
// R5 config (best measured): 128x128 tile, 8 warps (2x4), warp 64x32, K-chunk 64,
// 2-stage cp.async, 64KB smem (2 CTAs/SM). Fused sum/sumsq/rowmax epilogue.
// Mout is only 4B aligned -> scalar stores.
#define G_NCH 48
#define G_STAGE 32768
#define GEMM_SMEM 65536

__global__ void __launch_bounds__(256) k_gemm_mma(float* __restrict__ Mout) {
    extern __shared__ char sm[];
    uint32_t smb = smem_to_u32(sm);
    int tid = threadIdx.x, wid = tid >> 5, lane = tid & 31;
    int bx = blockIdx.x, by = blockIdx.y;
    const char* Ag = (const char*)g_Abf + (size_t)by * 128 * 6144;
    const char* Bg = (const char*)g_Bbf + (size_t)bx * 128 * 6144;

    int r_  = tid >> 3;
    int q16 = (tid & 7) * 16;
    int sw_ = r_ * 128 + (q16 ^ ((r_ & 7) << 4));

    // preload chunk 0 into stage 0
#pragma unroll
    for (int l = 0; l < 4; l++) {
        uint32_t so = sw_ + l * 4096;
        size_t   go = (size_t)(r_ + l * 32) * 6144 + q16;
        cpasync16(smb + so,         Ag + go);
        cpasync16(smb + 16384 + so, Bg + go);
    }
    CP_COMMIT(); CP_WAIT0();
    __syncthreads();

    int wm = wid & 1, wn = wid >> 1;
    int la15 = lane & 15, khalf = (lane >> 4) * 16;

    float acc[4][4][4];
#pragma unroll
    for (int ma = 0; ma < 4; ma++)
#pragma unroll
        for (int na = 0; na < 4; na++)
#pragma unroll
            for (int i = 0; i < 4; i++) acc[ma][na][i] = 0.f;

#pragma unroll 1
    for (int c = 0; c < G_NCH; c++) {
        uint32_t base = smb + (c & 1) * G_STAGE;
        if (c + 1 < G_NCH) {
            uint32_t dst = smb + ((c + 1) & 1) * G_STAGE;
            size_t kb = (size_t)(c + 1) * 128;
#pragma unroll
            for (int l = 0; l < 4; l++) {
                uint32_t so = sw_ + l * 4096;
                size_t   go = (size_t)(r_ + l * 32) * 6144 + kb + q16;
                cpasync16(dst + so,         Ag + go);
                cpasync16(dst + 16384 + so, Bg + go);
            }
            CP_COMMIT();
        }
#pragma unroll
        for (int k16 = 0; k16 < 4; k16++) {
            int cb = k16 * 32 + khalf;
            uint32_t a[4][4], b[2][4];
#pragma unroll
            for (int ma = 0; ma < 4; ma++) {
                int r = wm * 64 + ma * 16 + la15;
                ldsm4(a[ma], base + r * 128 + (cb ^ ((r & 7) << 4)));
            }
#pragma unroll
            for (int nb = 0; nb < 2; nb++) {
                int r = wn * 32 + nb * 16 + la15;
                ldsm4(b[nb], base + 16384 + r * 128 + (cb ^ ((r & 7) << 4)));
            }
#pragma unroll
            for (int ma = 0; ma < 4; ma++)
#pragma unroll
                for (int na = 0; na < 4; na++)
                    mma16816(acc[ma][na], a[ma], b[na >> 1][na & 1], b[na >> 1][(na & 1) + 2]);
        }
        if (c + 1 < G_NCH) CP_WAIT0();
        __syncthreads();
    }

    // ---- epilogue: scalar stores + fused stats ----
    int gid = lane >> 2, tig = lane & 3;
    float tsum = 0.f, tsq = 0.f;
#pragma unroll
    for (int ma = 0; ma < 4; ma++) {
        float rm0 = -1e30f, rm1 = -1e30f;
        int row = by * 128 + wm * 64 + ma * 16 + gid;
#pragma unroll
        for (int na = 0; na < 4; na++) {
            int col = bx * 128 + wn * 32 + na * 8 + tig * 2;
            float a0 = acc[ma][na][0], a1 = acc[ma][na][1];
            float a2 = acc[ma][na][2], a3 = acc[ma][na][3];
            float* p0 = Mout + (size_t)row * 4096 + col;
            float* p1 = Mout + (size_t)(row + 8) * 4096 + col;
            p0[0] = a0; p0[1] = a1; p1[0] = a2; p1[1] = a3;
            tsum += (a0 + a1) + (a2 + a3);
            tsq  += a0*a0 + a1*a1 + a2*a2 + a3*a3;
            rm0 = fmaxf(rm0, fmaxf(a0, a1));
            rm1 = fmaxf(rm1, fmaxf(a2, a3));
        }
        rm0 = fmaxf(rm0, __shfl_xor_sync(0xffffffffu, rm0, 1));
        rm0 = fmaxf(rm0, __shfl_xor_sync(0xffffffffu, rm0, 2));
        rm1 = fmaxf(rm1, __shfl_xor_sync(0xffffffffu, rm1, 1));
        rm1 = fmaxf(rm1, __shfl_xor_sync(0xffffffffu, rm1, 2));
        if (tig == 0) {
            atomicMax(&g_rowmax_u[row], fenc(rm0));
            atomicMax(&g_rowmax_u[row + 8], fenc(rm1));
        }
    }
    __shared__ float rsum[256], rsq[256];
    rsum[tid] = tsum; rsq[tid] = tsq; __syncthreads();
    for (int o = 128; o; o >>= 1) {
        if (tid < o) { rsum[tid] += rsum[tid + o]; rsq[tid] += rsq[tid + o]; }
        __syncthreads();
    }
    if (tid == 0) { atomicAdd(&g_sum, rsum[0]); atomicAdd(&g_sumsq, rsq[0]); }
}

// ======================= standardize M in place, build fp16 P0 (stats inlined) ==========
__global__ void k_makeP0(float* __restrict__ Mio) {
    __shared__ float sstat[2];
    int i = blockIdx.x, t = threadIdx.x;
    if (t == 0) {
        double s = (double)g_sum, s2 = (double)g_sumsq;
        double n = (double)NN;
        double mean = s / n;
        double var = (s2 - n * mean * mean) / (n - 1.0);   // ddof=1
        sstat[0] = (float)mean;
        sstat[1] = (float)(1.0 / sqrt(var));
    }
    __syncthreads();
    float mean = sstat[0], istd = sstat[1];
    float rmax = fdec(g_rowmax_u[i]);
    float* mrow = Mio + (size_t)i * N;
    __half2* prow = (__half2*)(g_P0h + (size_t)i * N);
#pragma unroll
    for (int k = 0; k < 8; k++) {
        int jp = t + 256 * k;                // pair index
        float m0 = mrow[2*jp], m1 = mrow[2*jp + 1];
        mrow[2*jp]     = (m0 - mean) * istd;
        mrow[2*jp + 1] = (m1 - mean) * istd;
        float e0 = __expf((m0 - rmax) * istd);
        float e1 = __expf((m1 - rmax) * istd);
        prow[jp] = __floats2half2_rn(e0, e1);
    }
}

// ======================= persistent fused Sinkhorn: 1 grid barrier / iteration ==========
// Per-iteration z accumulators (g_zit, pre-zeroed in k_init) remove in-loop zeroing and
// the second barrier. v kept redundantly in each block's smem -> identical decisions.
__global__ void __launch_bounds__(256) k_sinkall() {
    extern __shared__ char smraw[];
    float* v_sm = (float*)smraw;                           // 4096 floats  (16 KB)
    __half2* smrows = (__half2*)(smraw + 16384);           // 8 rows x 2048 half2 (64 KB)
    __shared__ float su[8];
    __shared__ float red[256];
    int t = threadIdx.x, w = t >> 5, lane = t & 31;

    for (int j = t; j < N; j += 256) v_sm[j] = 1.0f;
    __syncthreads();

    const float2* v2 = (const float2*)v_sm;
    int done = 0;

    for (int it = 0; it < 20 && !done; it++) {
        float za[16];
#pragma unroll
        for (int q = 0; q < 16; q++) za[q] = 0.f;

        for (int st = blockIdx.x; st < 512; st += NB) {
            int i0 = st * 8;
            {   // row pass: warp w -> row i0+w; stage row in smem, dot with v
                const __half2* row = (const __half2*)(g_P0h + (size_t)(i0 + w) * N);
                __half2* srow = smrows + (size_t)w * 2048;
                float acc = 0.f;
#pragma unroll 8
                for (int q = lane; q < 2048; q += 32) {
                    __half2 h = row[q];
                    srow[q] = h;
                    float2 f = __half22float2(h);
                    float2 vv = v2[q];
                    acc += f.x * vv.x + f.y * vv.y;
                }
#pragma unroll
                for (int o = 16; o; o >>= 1) acc += __shfl_down_sync(0xffffffffu, acc, o);
                if (lane == 0) su[w] = RC / acc;
            }
            __syncthreads();
#pragma unroll
            for (int kk = 0; kk < 8; kk++) {
                int j2 = t + kk * 256;
#pragma unroll
                for (int r = 0; r < 8; r++) {
                    float2 f = __half22float2(smrows[(size_t)r * 2048 + j2]);
                    float ur = su[r];
                    za[kk*2]     += f.x * ur;
                    za[kk*2 + 1] += f.y * ur;
                }
            }
            __syncthreads();
        }
        float* zb = g_zit[it];
#pragma unroll
        for (int kk = 0; kk < 8; kk++) {
            int j = (t + kk * 256) * 2;
            atomicAdd(&zb[j], za[kk*2]);
            atomicAdd(&zb[j + 1], za[kk*2 + 1]);
        }
        gbar();
        // check + v update (redundant in all blocks; identical data -> identical result)
        float md = 0.f;
        float znew[16];
#pragma unroll
        for (int kk = 0; kk < 16; kk++) {
            int j = t + kk * 256;
            float zj = __ldcg(&zb[j]);
            znew[kk] = zj;
            md = fmaxf(md, fabsf(v_sm[j] * zj - RC));
        }
        red[t] = md; __syncthreads();
        for (int o = 128; o; o >>= 1) {
            if (t < o) red[t] = fmaxf(red[t], red[t + o]);
            __syncthreads();
        }
        md = red[0];
        int newdone = done | (md <= OT_EPS);
        if (!newdone) {
#pragma unroll
            for (int kk = 0; kk < 16; kk++) {
                int j = t + kk * 256;
                v_sm[j] = RC / znew[kk];
            }
        }
        done = newdone;
        __syncthreads();
    }

    // final pass: w_i = 1/(P0 v)_i ; s = P0^T w
    float sa[16];
#pragma unroll
    for (int q = 0; q < 16; q++) sa[q] = 0.f;
    for (int st = blockIdx.x; st < 512; st += NB) {
        int i0 = st * 8;
        {
            const __half2* row = (const __half2*)(g_P0h + (size_t)(i0 + w) * N);
            __half2* srow = smrows + (size_t)w * 2048;
            float acc = 0.f;
#pragma unroll 8
            for (int q = lane; q < 2048; q += 32) {
                __half2 h = row[q];
                srow[q] = h;
                float2 f = __half22float2(h);
                float2 vv = v2[q];
                acc += f.x * vv.x + f.y * vv.y;
            }
#pragma unroll
            for (int o = 16; o; o >>= 1) acc += __shfl_down_sync(0xffffffffu, acc, o);
            if (lane == 0) { float uu = 1.0f / acc; su[w] = uu; g_w[i0 + w] = uu; }
        }
        __syncthreads();
#pragma unroll
        for (int kk = 0; kk < 8; kk++) {
            int j2 = t + kk * 256;
#pragma unroll
            for (int r = 0; r < 8; r++) {
                float2 f = __half22float2(smrows[(size_t)r * 2048 + j2]);
                float ur = su[r];
                sa[kk*2]     += f.x * ur;
                sa[kk*2 + 1] += f.y * ur;
            }
        }
        __syncthreads();
    }
#pragma unroll
    for (int kk = 0; kk < 8; kk++) {
        int j = (t + kk * 256) * 2;
        atomicAdd(&g_s[j], sa[kk*2]);
        atomicAdd(&g_s[j + 1], sa[kk*2 + 1]);
    }
    gbar();
    // sinv tail: block b handles 32 entries
    if (t < 32) {
        int j = blockIdx.x * 32 + t;
        g_sinv[j] = 1.0f / __ldcg(&g_s[j]);
    }
}

// ======================= final P = w_i * P0_ij * sinv_j ; loss partials =======================
__global__ void k_final(float* __restrict__ Pout) {
    int i = blockIdx.x, t = threadIdx.x;
    float wi = g_w[i];
    const __half2* row = (const __half2*)(g_P0h + (size_t)i * N);
    const float2* sv2 = (const float2*)g_sinv;
    float ss = 0.f;
#pragma unroll
    for (int k = 0; k < 8; k++) {
        int jp = t + 256 * k;
        float2 f = __half22float2(row[jp]);
        float2 si = sv2[jp];
        float o0 = wi * f.x * si.x;
        float o1 = wi * f.y * si.y;
        size_t base = (size_t)i * N + (size_t)jp * 2;
        Pout[base] = o0; Pout[base + 1] = o1;
        ss += o0*o0 + o1*o1;
        int j = jp * 2;
        if (i == j) atomicAdd(&g_pdiag, o0);
        else if (i == j + 1) atomicAdd(&g_pdiag, o1);
    }
    __shared__ float red[256];
    red[t] = ss; __syncthreads();
    for (int o = 128; o; o >>= 1) { if (t < o) red[t] += red[t + o]; __syncthreads(); }
    if (t == 0) atomicAdd(&g_psum, red[0]);
}

__global__ void k_loss(float* __restrict__ out) {
    out[0] = sqrtf(g_psum - 2.0f * g_pdiag + (float)N);
}

// ======================= launch =======================
extern "C" void kernel_launch(void* const* d_in, const int* in_sizes, int n_in,
                              void* d_out, int out_size) {
    const float* ft = (const float*)d_in[0];
    const float* fs = (const float*)d_in[1];
    float* out  = (float*)d_out;
    float* Pout = out + 1;
    float* Mout = out + 1 + NN;

    cudaFuncSetAttribute(k_gemm_mma, cudaFuncAttributeMaxDynamicSharedMemorySize, GEMM_SMEM);
    cudaFuncSetAttribute(k_sinkall,  cudaFuncAttributeMaxDynamicSharedMemorySize, 81920);

    k_init<<<128, 256>>>();
    k_prep<<<2 * N, 256>>>(ft, fs);
    k_gemm_mma<<<dim3(32, 32), 256, GEMM_SMEM>>>(Mout);
    k_makeP0<<<N, 256>>>(Mout);
    k_sinkall<<<NB, 256, 81920>>>();
    k_final<<<N, 256>>>(Pout);
    k_loss<<<1, 1>>>(out);
}

// round 10
// speedup vs baseline: 1.4987x; 1.3413x over previous
#include <cuda_runtime.h>
#include <cuda_fp16.h>
#include <cstdint>
#include <math.h>

#define N 4096
#define KDIM 1024
#define NN ((size_t)N*(size_t)N)
#define OT_EPS 1e-6f
#define RC (1.0f/4096.0f)
#define NB 128                   // persistent sinkhorn blocks (<= #SMs, all co-resident)

// ======================= PTX helpers (sm_80-level only: no tcgen05!) =======================
__device__ __forceinline__ uint32_t smem_to_u32(const void* smem_ptr) {
    uint32_t addr;
    asm("{ .reg .u64 tmp; cvta.to.shared.u64 tmp, %1; cvt.u32.u64 %0, tmp; }"
        : "=r"(addr) : "l"(smem_ptr));
    return addr;
}
__device__ __forceinline__ void cpasync16(uint32_t dst, const void* src) {
    asm volatile("cp.async.cg.shared.global [%0], [%1], 16;" :: "r"(dst), "l"(src));
}
#define CP_COMMIT() asm volatile("cp.async.commit_group;" ::: "memory")
#define CP_WAIT0()  asm volatile("cp.async.wait_group 0;" ::: "memory")

__device__ __forceinline__ void ldsm4(uint32_t* r, uint32_t addr) {
    asm volatile("ldmatrix.sync.aligned.m8n8.x4.shared.b16 {%0,%1,%2,%3}, [%4];"
        : "=r"(r[0]), "=r"(r[1]), "=r"(r[2]), "=r"(r[3]) : "r"(addr));
}
// fp16 inputs, fp32 accumulate
__device__ __forceinline__ void mma16816(float* d, const uint32_t* a, uint32_t b0, uint32_t b1) {
    asm volatile(
        "mma.sync.aligned.m16n8k16.row.col.f32.f16.f16.f32 "
        "{%0,%1,%2,%3}, {%4,%5,%6,%7}, {%8,%9}, {%0,%1,%2,%3};"
        : "+f"(d[0]), "+f"(d[1]), "+f"(d[2]), "+f"(d[3])
        : "r"(a[0]), "r"(a[1]), "r"(a[2]), "r"(a[3]), "r"(b0), "r"(b1));
}

// monotonic uint encoding for float atomicMax
__device__ __forceinline__ unsigned fenc(float f) {
    unsigned u = __float_as_uint(f);
    return (u & 0x80000000u) ? ~u : (u | 0x80000000u);
}
__device__ __forceinline__ float fdec(unsigned u) {
    return (u & 0x80000000u) ? __uint_as_float(u & 0x7fffffffu) : __uint_as_float(~u);
}

// ======================= device scratch =======================
__device__ __half g_P0h[16777216];               // 32 MB: exp(M' - rowmax') in fp16
__device__ __half g_Ahf[4096*2048];              // 16 MB: [A_hi | A_lo]
__device__ __half g_Bhf[4096*2048];              // 16 MB: [B_hi | B_hi]
__device__ float g_zit[21][N];                   // per-iteration z accumulators (pre-zeroed)
__device__ float g_w[N], g_s[N], g_sinv[N];
__device__ unsigned g_rowmax_u[N];
__device__ float g_sum, g_sumsq, g_psum, g_pdiag;
__device__ unsigned g_barcnt;
__device__ volatile unsigned g_bargen;

// DIY grid barrier: all NB blocks co-resident (1 block/SM).
__device__ __forceinline__ void gbar() {
    __syncthreads();
    if (threadIdx.x == 0) {
        __threadfence();
        unsigned arr = atomicAdd(&g_barcnt, 1u) + 1u;
        unsigned gen = (arr + NB - 1u) / NB;
        if (arr == gen * NB) {
            g_bargen = gen;
        } else {
            while (g_bargen < gen) { }
        }
    }
    __syncthreads();
}

// ======================= init (re-runs on every graph replay) =======================
__global__ void k_init() {
    int gid = blockIdx.x * 256 + threadIdx.x;           // 32768 threads
    if (gid == 0) {
        g_sum = 0.f; g_sumsq = 0.f; g_psum = 0.f; g_pdiag = 0.f;
        g_barcnt = 0u; g_bargen = 0u;
    }
    float* zflat = &g_zit[0][0];
    for (int j = gid; j < 21 * N; j += 32768) zflat[j] = 0.f;
    if (gid < N) { g_s[gid] = 0.f; g_rowmax_u[gid] = 0u; }
}

// ======================= fused rownorm + fp16 2-product split conversion ================
// A' K-slices: [hi, lo] ; B' K-slices: [hi, hi]
// A'.B'^T over K=2048 = (ah+al)*bh ~= a*bh ; error = a*b_lo ~ 2.4e-4 relative.
__global__ void k_prep(const float* __restrict__ ft, const float* __restrict__ fs) {
    int row = blockIdx.x;
    int t = threadIdx.x;
    bool isA = row < N;
    int r = isA ? row : row - N;
    const float* src = (isA ? ft : fs) + (size_t)r * KDIM;
    float4 v = ((const float4*)src)[t];
    float ss = v.x*v.x + v.y*v.y + v.z*v.z + v.w*v.w;
    __shared__ float red[256];
    red[t] = ss; __syncthreads();
    for (int o = 128; o; o >>= 1) { if (t < o) red[t] += red[t + o]; __syncthreads(); }
    float rinv = 1.0f / fmaxf(sqrtf(red[0]), 1e-12f);

    __half* dst = (isA ? g_Ahf : g_Bhf) + (size_t)r * 2048;
    float x0 = v.x * rinv, x1 = v.y * rinv, x2 = v.z * rinv, x3 = v.w * rinv;
    __half h0 = __float2half(x0), h1 = __float2half(x1);
    __half h2 = __float2half(x2), h3 = __float2half(x3);
    __half2 hh0 = __halves2half2(h0, h1), hh1 = __halves2half2(h2, h3);
    __half2* d2 = (__half2*)dst;
    int c2 = t * 2;
    d2[c2] = hh0; d2[c2 + 1] = hh1;                       // slice 0: hi
    if (isA) {
        __half l0 = __float2half(x0 - __half2float(h0));
        __half l1 = __float2half(x1 - __half2float(h1));
        __half l2 = __float2half(x2 - __half2float(h2));
        __half l3 = __float2half(x3 - __half2float(h3));
        __half2 ll0 = __halves2half2(l0, l1), ll1 = __halves2half2(l2, l3);
        d2[512 + c2] = ll0; d2[512 + c2 + 1] = ll1;       // slice 1: lo
    } else {
        d2[512 + c2] = hh0; d2[512 + c2 + 1] = hh1;       // slice 1: hi (duplicate)
    }
}

// ======================= mma.sync fp16 GEMM + fused stats, K=2048 =======================
// Best-measured config: 128x128 tile, 8 warps (2x4), warp 64x32, K-chunk 64,
// 2-stage cp.async, 64KB smem (2 CTAs/SM). Fused sum/sumsq/rowmax epilogue.
// Mout is only 4B aligned -> scalar stores.
#define G_NCH 32
#define G_STAGE 32768
#define GEMM_SMEM 65536
#define KROWB 4096               // bytes per row of A'/B' (2048 halves)

__global__ void __launch_bounds__(256) k_gemm_mma(float* __restrict__ Mout) {
    extern __shared__ char sm[];
    uint32_t smb = smem_to_u32(sm);
    int tid = threadIdx.x, wid = tid >> 5, lane = tid & 31;
    int bx = blockIdx.x, by = blockIdx.y;
    const char* Ag = (const char*)g_Ahf + (size_t)by * 128 * KROWB;
    const char* Bg = (const char*)g_Bhf + (size_t)bx * 128 * KROWB;

    int r_  = tid >> 3;
    int q16 = (tid & 7) * 16;
    int sw_ = r_ * 128 + (q16 ^ ((r_ & 7) << 4));

    // preload chunk 0 into stage 0
#pragma unroll
    for (int l = 0; l < 4; l++) {
        uint32_t so = sw_ + l * 4096;
        size_t   go = (size_t)(r_ + l * 32) * KROWB + q16;
        cpasync16(smb + so,         Ag + go);
        cpasync16(smb + 16384 + so, Bg + go);
    }
    CP_COMMIT(); CP_WAIT0();
    __syncthreads();

    int wm = wid & 1, wn = wid >> 1;
    int la15 = lane & 15, khalf = (lane >> 4) * 16;

    float acc[4][4][4];
#pragma unroll
    for (int ma = 0; ma < 4; ma++)
#pragma unroll
        for (int na = 0; na < 4; na++)
#pragma unroll
            for (int i = 0; i < 4; i++) acc[ma][na][i] = 0.f;

#pragma unroll 1
    for (int c = 0; c < G_NCH; c++) {
        uint32_t base = smb + (c & 1) * G_STAGE;
        if (c + 1 < G_NCH) {
            uint32_t dst = smb + ((c + 1) & 1) * G_STAGE;
            size_t kb = (size_t)(c + 1) * 128;
#pragma unroll
            for (int l = 0; l < 4; l++) {
                uint32_t so = sw_ + l * 4096;
                size_t   go = (size_t)(r_ + l * 32) * KROWB + kb + q16;
                cpasync16(dst + so,         Ag + go);
                cpasync16(dst + 16384 + so, Bg + go);
            }
            CP_COMMIT();
        }
#pragma unroll
        for (int k16 = 0; k16 < 4; k16++) {
            int cb = k16 * 32 + khalf;
            uint32_t a[4][4], b[2][4];
#pragma unroll
            for (int ma = 0; ma < 4; ma++) {
                int r = wm * 64 + ma * 16 + la15;
                ldsm4(a[ma], base + r * 128 + (cb ^ ((r & 7) << 4)));
            }
#pragma unroll
            for (int nb = 0; nb < 2; nb++) {
                int r = wn * 32 + nb * 16 + la15;
                ldsm4(b[nb], base + 16384 + r * 128 + (cb ^ ((r & 7) << 4)));
            }
#pragma unroll
            for (int ma = 0; ma < 4; ma++)
#pragma unroll
                for (int na = 0; na < 4; na++)
                    mma16816(acc[ma][na], a[ma], b[na >> 1][na & 1], b[na >> 1][(na & 1) + 2]);
        }
        if (c + 1 < G_NCH) CP_WAIT0();
        __syncthreads();
    }

    // ---- epilogue: scalar stores + fused stats ----
    int gid = lane >> 2, tig = lane & 3;
    float tsum = 0.f, tsq = 0.f;
#pragma unroll
    for (int ma = 0; ma < 4; ma++) {
        float rm0 = -1e30f, rm1 = -1e30f;
        int row = by * 128 + wm * 64 + ma * 16 + gid;
#pragma unroll
        for (int na = 0; na < 4; na++) {
            int col = bx * 128 + wn * 32 + na * 8 + tig * 2;
            float a0 = acc[ma][na][0], a1 = acc[ma][na][1];
            float a2 = acc[ma][na][2], a3 = acc[ma][na][3];
            float* p0 = Mout + (size_t)row * 4096 + col;
            float* p1 = Mout + (size_t)(row + 8) * 4096 + col;
            p0[0] = a0; p0[1] = a1; p1[0] = a2; p1[1] = a3;
            tsum += (a0 + a1) + (a2 + a3);
            tsq  += a0*a0 + a1*a1 + a2*a2 + a3*a3;
            rm0 = fmaxf(rm0, fmaxf(a0, a1));
            rm1 = fmaxf(rm1, fmaxf(a2, a3));
        }
        rm0 = fmaxf(rm0, __shfl_xor_sync(0xffffffffu, rm0, 1));
        rm0 = fmaxf(rm0, __shfl_xor_sync(0xffffffffu, rm0, 2));
        rm1 = fmaxf(rm1, __shfl_xor_sync(0xffffffffu, rm1, 1));
        rm1 = fmaxf(rm1, __shfl_xor_sync(0xffffffffu, rm1, 2));
        if (tig == 0) {
            atomicMax(&g_rowmax_u[row], fenc(rm0));
            atomicMax(&g_rowmax_u[row + 8], fenc(rm1));
        }
    }
    __shared__ float rsum[256], rsq[256];
    rsum[tid] = tsum; rsq[tid] = tsq; __syncthreads();
    for (int o = 128; o; o >>= 1) {
        if (tid < o) { rsum[tid] += rsum[tid + o]; rsq[tid] += rsq[tid + o]; }
        __syncthreads();
    }
    if (tid == 0) { atomicAdd(&g_sum, rsum[0]); atomicAdd(&g_sumsq, rsq[0]); }
}

// ======================= standardize M in place, build fp16 P0 (stats inlined) ==========
__global__ void k_makeP0(float* __restrict__ Mio) {
    __shared__ float sstat[2];
    int i = blockIdx.x, t = threadIdx.x;
    if (t == 0) {
        double s = (double)g_sum, s2 = (double)g_sumsq;
        double n = (double)NN;
        double mean = s / n;
        double var = (s2 - n * mean * mean) / (n - 1.0);   // ddof=1
        sstat[0] = (float)mean;
        sstat[1] = (float)(1.0 / sqrt(var));
    }
    __syncthreads();
    float mean = sstat[0], istd = sstat[1];
    float rmax = fdec(g_rowmax_u[i]);
    float* mrow = Mio + (size_t)i * N;
    __half2* prow = (__half2*)(g_P0h + (size_t)i * N);
#pragma unroll
    for (int k = 0; k < 8; k++) {
        int jp = t + 256 * k;                // pair index
        float m0 = __ldcs(&mrow[2*jp]);
        float m1 = __ldcs(&mrow[2*jp + 1]);
        __stcs(&mrow[2*jp],     (m0 - mean) * istd);   // M never re-read: stream past L2
        __stcs(&mrow[2*jp + 1], (m1 - mean) * istd);
        float e0 = __expf((m0 - rmax) * istd);
        float e1 = __expf((m1 - rmax) * istd);
        prow[jp] = __floats2half2_rn(e0, e1);
    }
}

// ======================= persistent fused Sinkhorn: 1 grid barrier / iteration ==========
__global__ void __launch_bounds__(256) k_sinkall() {
    extern __shared__ char smraw[];
    float* v_sm = (float*)smraw;                           // 4096 floats  (16 KB)
    __half2* smrows = (__half2*)(smraw + 16384);           // 8 rows x 2048 half2 (64 KB)
    __shared__ float su[8];
    __shared__ float red[256];
    int t = threadIdx.x, w = t >> 5, lane = t & 31;

    for (int j = t; j < N; j += 256) v_sm[j] = 1.0f;
    __syncthreads();

    const float2* v2 = (const float2*)v_sm;
    int done = 0;

    for (int it = 0; it < 20 && !done; it++) {
        float za[16];
#pragma unroll
        for (int q = 0; q < 16; q++) za[q] = 0.f;

        for (int st = blockIdx.x; st < 512; st += NB) {
            int i0 = st * 8;
            {   // row pass: warp w -> row i0+w; stage row in smem, dot with v
                const __half2* row = (const __half2*)(g_P0h + (size_t)(i0 + w) * N);
                __half2* srow = smrows + (size_t)w * 2048;
                float acc = 0.f;
#pragma unroll 8
                for (int q = lane; q < 2048; q += 32) {
                    __half2 h = row[q];
                    srow[q] = h;
                    float2 f = __half22float2(h);
                    float2 vv = v2[q];
                    acc += f.x * vv.x + f.y * vv.y;
                }
#pragma unroll
                for (int o = 16; o; o >>= 1) acc += __shfl_down_sync(0xffffffffu, acc, o);
                if (lane == 0) su[w] = RC / acc;
            }
            __syncthreads();
#pragma unroll
            for (int kk = 0; kk < 8; kk++) {
                int j2 = t + kk * 256;
#pragma unroll
                for (int r = 0; r < 8; r++) {
                    float2 f = __half22float2(smrows[(size_t)r * 2048 + j2]);
                    float ur = su[r];
                    za[kk*2]     += f.x * ur;
                    za[kk*2 + 1] += f.y * ur;
                }
            }
            __syncthreads();
        }
        float* zb = g_zit[it];
#pragma unroll
        for (int kk = 0; kk < 8; kk++) {
            int j = (t + kk * 256) * 2;
            atomicAdd(&zb[j], za[kk*2]);
            atomicAdd(&zb[j + 1], za[kk*2 + 1]);
        }
        gbar();
        // check + v update (redundant in all blocks; identical data -> identical result)
        float md = 0.f;
        float znew[16];
#pragma unroll
        for (int kk = 0; kk < 16; kk++) {
            int j = t + kk * 256;
            float zj = __ldcg(&zb[j]);
            znew[kk] = zj;
            md = fmaxf(md, fabsf(v_sm[j] * zj - RC));
        }
        red[t] = md; __syncthreads();
        for (int o = 128; o; o >>= 1) {
            if (t < o) red[t] = fmaxf(red[t], red[t + o]);
            __syncthreads();
        }
        md = red[0];
        int newdone = done | (md <= OT_EPS);
        if (!newdone) {
#pragma unroll
            for (int kk = 0; kk < 16; kk++) {
                int j = t + kk * 256;
                v_sm[j] = RC / znew[kk];
            }
        }
        done = newdone;
        __syncthreads();
    }

    // final pass: w_i = 1/(P0 v)_i ; s = P0^T w
    float sa[16];
#pragma unroll
    for (int q = 0; q < 16; q++) sa[q] = 0.f;
    for (int st = blockIdx.x; st < 512; st += NB) {
        int i0 = st * 8;
        {
            const __half2* row = (const __half2*)(g_P0h + (size_t)(i0 + w) * N);
            __half2* srow = smrows + (size_t)w * 2048;
            float acc = 0.f;
#pragma unroll 8
            for (int q = lane; q < 2048; q += 32) {
                __half2 h = row[q];
                srow[q] = h;
                float2 f = __half22float2(h);
                float2 vv = v2[q];
                acc += f.x * vv.x + f.y * vv.y;
            }
#pragma unroll
            for (int o = 16; o; o >>= 1) acc += __shfl_down_sync(0xffffffffu, acc, o);
            if (lane == 0) { float uu = 1.0f / acc; su[w] = uu; g_w[i0 + w] = uu; }
        }
        __syncthreads();
#pragma unroll
        for (int kk = 0; kk < 8; kk++) {
            int j2 = t + kk * 256;
#pragma unroll
            for (int r = 0; r < 8; r++) {
                float2 f = __half22float2(smrows[(size_t)r * 2048 + j2]);
                float ur = su[r];
                sa[kk*2]     += f.x * ur;
                sa[kk*2 + 1] += f.y * ur;
            }
        }
        __syncthreads();
    }
#pragma unroll
    for (int kk = 0; kk < 8; kk++) {
        int j = (t + kk * 256) * 2;
        atomicAdd(&g_s[j], sa[kk*2]);
        atomicAdd(&g_s[j + 1], sa[kk*2 + 1]);
    }
    gbar();
    // sinv tail: block b handles 32 entries
    if (t < 32) {
        int j = blockIdx.x * 32 + t;
        g_sinv[j] = 1.0f / __ldcg(&g_s[j]);
    }
}

// ======================= final P = w_i * P0_ij * sinv_j ; loss partials =======================
__global__ void k_final(float* __restrict__ Pout) {
    int i = blockIdx.x, t = threadIdx.x;
    float wi = g_w[i];
    const __half2* row = (const __half2*)(g_P0h + (size_t)i * N);
    const float2* sv2 = (const float2*)g_sinv;
    float ss = 0.f;
#pragma unroll
    for (int k = 0; k < 8; k++) {
        int jp = t + 256 * k;
        float2 f = __half22float2(row[jp]);
        float2 si = sv2[jp];
        float o0 = wi * f.x * si.x;
        float o1 = wi * f.y * si.y;
        size_t base = (size_t)i * N + (size_t)jp * 2;
        __stcs(&Pout[base], o0);
        __stcs(&Pout[base + 1], o1);
        ss += o0*o0 + o1*o1;
        int j = jp * 2;
        if (i == j) atomicAdd(&g_pdiag, o0);
        else if (i == j + 1) atomicAdd(&g_pdiag, o1);
    }
    __shared__ float red[256];
    red[t] = ss; __syncthreads();
    for (int o = 128; o; o >>= 1) { if (t < o) red[t] += red[t + o]; __syncthreads(); }
    if (t == 0) atomicAdd(&g_psum, red[0]);
}

__global__ void k_loss(float* __restrict__ out) {
    out[0] = sqrtf(g_psum - 2.0f * g_pdiag + (float)N);
}

// ======================= launch =======================
extern "C" void kernel_launch(void* const* d_in, const int* in_sizes, int n_in,
                              void* d_out, int out_size) {
    const float* ft = (const float*)d_in[0];
    const float* fs = (const float*)d_in[1];
    float* out  = (float*)d_out;
    float* Pout = out + 1;
    float* Mout = out + 1 + NN;

    cudaFuncSetAttribute(k_gemm_mma, cudaFuncAttributeMaxDynamicSharedMemorySize, GEMM_SMEM);
    cudaFuncSetAttribute(k_sinkall,  cudaFuncAttributeMaxDynamicSharedMemorySize, 81920);

    k_init<<<128, 256>>>();
    k_prep<<<2 * N, 256>>>(ft, fs);
    k_gemm_mma<<<dim3(32, 32), 256, GEMM_SMEM>>>(Mout);
    k_makeP0<<<N, 256>>>(Mout);
    k_sinkall<<<NB, 256, 81920>>>();
    k_final<<<N, 256>>>(Pout);
    k_loss<<<1, 1>>>(out);
}

// round 11
// speedup vs baseline: 2.0962x; 1.3987x over previous
#include <cuda_runtime.h>
#include <cuda_fp16.h>
#include <cstdint>
#include <math.h>

#define N 4096
#define KDIM 1024
#define NN ((size_t)N*(size_t)N)
#define OT_EPS 1e-6f
#define RC (1.0f/4096.0f)
#define NB 128                   // persistent sinkhorn blocks (<= #SMs, all co-resident)

// ======================= PTX helpers (sm_80-level only: no tcgen05!) =======================
__device__ __forceinline__ uint32_t smem_to_u32(const void* smem_ptr) {
    uint32_t addr;
    asm("{ .reg .u64 tmp; cvta.to.shared.u64 tmp, %1; cvt.u32.u64 %0, tmp; }"
        : "=r"(addr) : "l"(smem_ptr));
    return addr;
}
__device__ __forceinline__ void cpasync16(uint32_t dst, const void* src) {
    asm volatile("cp.async.cg.shared.global [%0], [%1], 16;" :: "r"(dst), "l"(src));
}
#define CP_COMMIT() asm volatile("cp.async.commit_group;" ::: "memory")
#define CP_WAIT0()  asm volatile("cp.async.wait_group 0;" ::: "memory")

__device__ __forceinline__ void ldsm4(uint32_t* r, uint32_t addr) {
    asm volatile("ldmatrix.sync.aligned.m8n8.x4.shared.b16 {%0,%1,%2,%3}, [%4];"
        : "=r"(r[0]), "=r"(r[1]), "=r"(r[2]), "=r"(r[3]) : "r"(addr));
}
// fp16 inputs, fp32 accumulate
__device__ __forceinline__ void mma16816(float* d, const uint32_t* a, uint32_t b0, uint32_t b1) {
    asm volatile(
        "mma.sync.aligned.m16n8k16.row.col.f32.f16.f16.f32 "
        "{%0,%1,%2,%3}, {%4,%5,%6,%7}, {%8,%9}, {%0,%1,%2,%3};"
        : "+f"(d[0]), "+f"(d[1]), "+f"(d[2]), "+f"(d[3])
        : "r"(a[0]), "r"(a[1]), "r"(a[2]), "r"(a[3]), "r"(b0), "r"(b1));
}

// monotonic uint encoding for float atomicMax
__device__ __forceinline__ unsigned fenc(float f) {
    unsigned u = __float_as_uint(f);
    return (u & 0x80000000u) ? ~u : (u | 0x80000000u);
}
__device__ __forceinline__ float fdec(unsigned u) {
    return (u & 0x80000000u) ? __uint_as_float(u & 0x7fffffffu) : __uint_as_float(~u);
}

// ======================= device scratch =======================
__device__ __half g_P0h[16777216];               // 32 MB: exp(M' - rowmax') in fp16
__device__ __half g_Ahf[4096*1024];              // 8 MB: normalized A rows, fp16
__device__ __half g_Bhf[4096*1024];              // 8 MB: normalized B rows, fp16
__device__ float g_zit[21][N];                   // per-iteration z accumulators (pre-zeroed)
__device__ float g_w[N], g_s[N], g_sinv[N];
__device__ unsigned g_rowmax_u[N];
__device__ float g_sum, g_sumsq, g_psum, g_pdiag;
__device__ unsigned g_barcnt;
__device__ volatile unsigned g_bargen;

// DIY grid barrier: all NB blocks co-resident (1 block/SM).
__device__ __forceinline__ void gbar() {
    __syncthreads();
    if (threadIdx.x == 0) {
        __threadfence();
        unsigned arr = atomicAdd(&g_barcnt, 1u) + 1u;
        unsigned gen = (arr + NB - 1u) / NB;
        if (arr == gen * NB) {
            g_bargen = gen;
        } else {
            while (g_bargen < gen) { }
        }
    }
    __syncthreads();
}

// ======================= init (re-runs on every graph replay) =======================
__global__ void k_init() {
    int gid = blockIdx.x * 256 + threadIdx.x;           // 32768 threads
    if (gid == 0) {
        g_sum = 0.f; g_sumsq = 0.f; g_psum = 0.f; g_pdiag = 0.f;
        g_barcnt = 0u; g_bargen = 0u;
    }
    float* zflat = &g_zit[0][0];
    for (int j = gid; j < 21 * N; j += 32768) zflat[j] = 0.f;
    if (gid < N) { g_s[gid] = 0.f; g_rowmax_u[gid] = 0u; }
}

// ======================= fused rownorm + fp16 conversion (K=1024, no split) ==============
__global__ void k_prep(const float* __restrict__ ft, const float* __restrict__ fs) {
    int row = blockIdx.x;
    int t = threadIdx.x;
    bool isA = row < N;
    int r = isA ? row : row - N;
    const float* src = (isA ? ft : fs) + (size_t)r * KDIM;
    float4 v = ((const float4*)src)[t];
    float ss = v.x*v.x + v.y*v.y + v.z*v.z + v.w*v.w;
    __shared__ float red[256];
    red[t] = ss; __syncthreads();
    for (int o = 128; o; o >>= 1) { if (t < o) red[t] += red[t + o]; __syncthreads(); }
    float rinv = 1.0f / fmaxf(sqrtf(red[0]), 1e-12f);

    __half2* d2 = (__half2*)((isA ? g_Ahf : g_Bhf) + (size_t)r * 1024);
    float x0 = v.x * rinv, x1 = v.y * rinv, x2 = v.z * rinv, x3 = v.w * rinv;
    int c2 = t * 2;
    d2[c2]     = __halves2half2(__float2half(x0), __float2half(x1));
    d2[c2 + 1] = __halves2half2(__float2half(x2), __float2half(x3));
}

// ======================= mma.sync fp16 GEMM + fused stats, K=1024 =======================
// Best-measured config: 128x128 tile, 8 warps (2x4), warp 64x32, K-chunk 64,
// 2-stage cp.async, 64KB smem (2 CTAs/SM). Fused sum/sumsq/rowmax epilogue.
// Mout is only 4B aligned -> scalar stores.
#define G_NCH 16
#define G_STAGE 32768
#define GEMM_SMEM 65536
#define KROWB 2048               // bytes per row of A'/B' (1024 halves)

__global__ void __launch_bounds__(256) k_gemm_mma(float* __restrict__ Mout) {
    extern __shared__ char sm[];
    uint32_t smb = smem_to_u32(sm);
    int tid = threadIdx.x, wid = tid >> 5, lane = tid & 31;
    int bx = blockIdx.x, by = blockIdx.y;
    const char* Ag = (const char*)g_Ahf + (size_t)by * 128 * KROWB;
    const char* Bg = (const char*)g_Bhf + (size_t)bx * 128 * KROWB;

    int r_  = tid >> 3;
    int q16 = (tid & 7) * 16;
    int sw_ = r_ * 128 + (q16 ^ ((r_ & 7) << 4));

    // preload chunk 0 into stage 0
#pragma unroll
    for (int l = 0; l < 4; l++) {
        uint32_t so = sw_ + l * 4096;
        size_t   go = (size_t)(r_ + l * 32) * KROWB + q16;
        cpasync16(smb + so,         Ag + go);
        cpasync16(smb + 16384 + so, Bg + go);
    }
    CP_COMMIT(); CP_WAIT0();
    __syncthreads();

    int wm = wid & 1, wn = wid >> 1;
    int la15 = lane & 15, khalf = (lane >> 4) * 16;

    float acc[4][4][4];
#pragma unroll
    for (int ma = 0; ma < 4; ma++)
#pragma unroll
        for (int na = 0; na < 4; na++)
#pragma unroll
            for (int i = 0; i < 4; i++) acc[ma][na][i] = 0.f;

#pragma unroll 1
    for (int c = 0; c < G_NCH; c++) {
        uint32_t base = smb + (c & 1) * G_STAGE;
        if (c + 1 < G_NCH) {
            uint32_t dst = smb + ((c + 1) & 1) * G_STAGE;
            size_t kb = (size_t)(c + 1) * 128;
#pragma unroll
            for (int l = 0; l < 4; l++) {
                uint32_t so = sw_ + l * 4096;
                size_t   go = (size_t)(r_ + l * 32) * KROWB + kb + q16;
                cpasync16(dst + so,         Ag + go);
                cpasync16(dst + 16384 + so, Bg + go);
            }
            CP_COMMIT();
        }
#pragma unroll
        for (int k16 = 0; k16 < 4; k16++) {
            int cb = k16 * 32 + khalf;
            uint32_t a[4][4], b[2][4];
#pragma unroll
            for (int ma = 0; ma < 4; ma++) {
                int r = wm * 64 + ma * 16 + la15;
                ldsm4(a[ma], base + r * 128 + (cb ^ ((r & 7) << 4)));
            }
#pragma unroll
            for (int nb = 0; nb < 2; nb++) {
                int r = wn * 32 + nb * 16 + la15;
                ldsm4(b[nb], base + 16384 + r * 128 + (cb ^ ((r & 7) << 4)));
            }
#pragma unroll
            for (int ma = 0; ma < 4; ma++)
#pragma unroll
                for (int na = 0; na < 4; na++)
                    mma16816(acc[ma][na], a[ma], b[na >> 1][na & 1], b[na >> 1][(na & 1) + 2]);
        }
        if (c + 1 < G_NCH) CP_WAIT0();
        __syncthreads();
    }

    // ---- epilogue: scalar stores + fused stats ----
    int gid = lane >> 2, tig = lane & 3;
    float tsum = 0.f, tsq = 0.f;
#pragma unroll
    for (int ma = 0; ma < 4; ma++) {
        float rm0 = -1e30f, rm1 = -1e30f;
        int row = by * 128 + wm * 64 + ma * 16 + gid;
#pragma unroll
        for (int na = 0; na < 4; na++) {
            int col = bx * 128 + wn * 32 + na * 8 + tig * 2;
            float a0 = acc[ma][na][0], a1 = acc[ma][na][1];
            float a2 = acc[ma][na][2], a3 = acc[ma][na][3];
            float* p0 = Mout + (size_t)row * 4096 + col;
            float* p1 = Mout + (size_t)(row + 8) * 4096 + col;
            p0[0] = a0; p0[1] = a1; p1[0] = a2; p1[1] = a3;
            tsum += (a0 + a1) + (a2 + a3);
            tsq  += a0*a0 + a1*a1 + a2*a2 + a3*a3;
            rm0 = fmaxf(rm0, fmaxf(a0, a1));
            rm1 = fmaxf(rm1, fmaxf(a2, a3));
        }
        rm0 = fmaxf(rm0, __shfl_xor_sync(0xffffffffu, rm0, 1));
        rm0 = fmaxf(rm0, __shfl_xor_sync(0xffffffffu, rm0, 2));
        rm1 = fmaxf(rm1, __shfl_xor_sync(0xffffffffu, rm1, 1));
        rm1 = fmaxf(rm1, __shfl_xor_sync(0xffffffffu, rm1, 2));
        if (tig == 0) {
            atomicMax(&g_rowmax_u[row], fenc(rm0));
            atomicMax(&g_rowmax_u[row + 8], fenc(rm1));
        }
    }
    __shared__ float rsum[256], rsq[256];
    rsum[tid] = tsum; rsq[tid] = tsq; __syncthreads();
    for (int o = 128; o; o >>= 1) {
        if (tid < o) { rsum[tid] += rsum[tid + o]; rsq[tid] += rsq[tid + o]; }
        __syncthreads();
    }
    if (tid == 0) { atomicAdd(&g_sum, rsum[0]); atomicAdd(&g_sumsq, rsq[0]); }
}

// ======================= standardize M in place, build fp16 P0 (stats inlined) ==========
__global__ void k_makeP0(float* __restrict__ Mio) {
    __shared__ float sstat[2];
    int i = blockIdx.x, t = threadIdx.x;
    if (t == 0) {
        double s = (double)g_sum, s2 = (double)g_sumsq;
        double n = (double)NN;
        double mean = s / n;
        double var = (s2 - n * mean * mean) / (n - 1.0);   // ddof=1
        sstat[0] = (float)mean;
        sstat[1] = (float)(1.0 / sqrt(var));
    }
    __syncthreads();
    float mean = sstat[0], istd = sstat[1];
    float rmax = fdec(g_rowmax_u[i]);
    float* mrow = Mio + (size_t)i * N;
    __half2* prow = (__half2*)(g_P0h + (size_t)i * N);
#pragma unroll
    for (int k = 0; k < 8; k++) {
        int jp = t + 256 * k;                // pair index
        float m0 = __ldcs(&mrow[2*jp]);
        float m1 = __ldcs(&mrow[2*jp + 1]);
        __stcs(&mrow[2*jp],     (m0 - mean) * istd);   // M never re-read: stream past L2
        __stcs(&mrow[2*jp + 1], (m1 - mean) * istd);
        float e0 = __expf((m0 - rmax) * istd);
        float e1 = __expf((m1 - rmax) * istd);
        prow[jp] = __floats2half2_rn(e0, e1);
    }
}

// ======================= persistent fused Sinkhorn: 1 grid barrier / iteration ==========
__global__ void __launch_bounds__(256) k_sinkall() {
    extern __shared__ char smraw[];
    float* v_sm = (float*)smraw;                           // 4096 floats  (16 KB)
    __half2* smrows = (__half2*)(smraw + 16384);           // 8 rows x 2048 half2 (64 KB)
    __shared__ float su[8];
    __shared__ float red[256];
    int t = threadIdx.x, w = t >> 5, lane = t & 31;

    for (int j = t; j < N; j += 256) v_sm[j] = 1.0f;
    __syncthreads();

    const float2* v2 = (const float2*)v_sm;
    int done = 0;

    for (int it = 0; it < 20 && !done; it++) {
        float za[16];
#pragma unroll
        for (int q = 0; q < 16; q++) za[q] = 0.f;

        for (int st = blockIdx.x; st < 512; st += NB) {
            int i0 = st * 8;
            {   // row pass: warp w -> row i0+w; stage row in smem, dot with v
                const __half2* row = (const __half2*)(g_P0h + (size_t)(i0 + w) * N);
                __half2* srow = smrows + (size_t)w * 2048;
                float acc = 0.f;
#pragma unroll 8
                for (int q = lane; q < 2048; q += 32) {
                    __half2 h = row[q];
                    srow[q] = h;
                    float2 f = __half22float2(h);
                    float2 vv = v2[q];
                    acc += f.x * vv.x + f.y * vv.y;
                }
#pragma unroll
                for (int o = 16; o; o >>= 1) acc += __shfl_down_sync(0xffffffffu, acc, o);
                if (lane == 0) su[w] = RC / acc;
            }
            __syncthreads();
#pragma unroll
            for (int kk = 0; kk < 8; kk++) {
                int j2 = t + kk * 256;
#pragma unroll
                for (int r = 0; r < 8; r++) {
                    float2 f = __half22float2(smrows[(size_t)r * 2048 + j2]);
                    float ur = su[r];
                    za[kk*2]     += f.x * ur;
                    za[kk*2 + 1] += f.y * ur;
                }
            }
            __syncthreads();
        }
        float* zb = g_zit[it];
#pragma unroll
        for (int kk = 0; kk < 8; kk++) {
            int j = (t + kk * 256) * 2;
            atomicAdd(&zb[j], za[kk*2]);
            atomicAdd(&zb[j + 1], za[kk*2 + 1]);
        }
        gbar();
        // check + v update (redundant in all blocks; identical data -> identical result)
        float md = 0.f;
        float znew[16];
#pragma unroll
        for (int kk = 0; kk < 16; kk++) {
            int j = t + kk * 256;
            float zj = __ldcg(&zb[j]);
            znew[kk] = zj;
            md = fmaxf(md, fabsf(v_sm[j] * zj - RC));
        }
        red[t] = md; __syncthreads();
        for (int o = 128; o; o >>= 1) {
            if (t < o) red[t] = fmaxf(red[t], red[t + o]);
            __syncthreads();
        }
        md = red[0];
        int newdone = done | (md <= OT_EPS);
        if (!newdone) {
#pragma unroll
            for (int kk = 0; kk < 16; kk++) {
                int j = t + kk * 256;
                v_sm[j] = RC / znew[kk];
            }
        }
        done = newdone;
        __syncthreads();
    }

    // final pass: w_i = 1/(P0 v)_i ; s = P0^T w
    float sa[16];
#pragma unroll
    for (int q = 0; q < 16; q++) sa[q] = 0.f;
    for (int st = blockIdx.x; st < 512; st += NB) {
        int i0 = st * 8;
        {
            const __half2* row = (const __half2*)(g_P0h + (size_t)(i0 + w) * N);
            __half2* srow = smrows + (size_t)w * 2048;
            float acc = 0.f;
#pragma unroll 8
            for (int q = lane; q < 2048; q += 32) {
                __half2 h = row[q];
                srow[q] = h;
                float2 f = __half22float2(h);
                float2 vv = v2[q];
                acc += f.x * vv.x + f.y * vv.y;
            }
#pragma unroll
            for (int o = 16; o; o >>= 1) acc += __shfl_down_sync(0xffffffffu, acc, o);
            if (lane == 0) { float uu = 1.0f / acc; su[w] = uu; g_w[i0 + w] = uu; }
        }
        __syncthreads();
#pragma unroll
        for (int kk = 0; kk < 8; kk++) {
            int j2 = t + kk * 256;
#pragma unroll
            for (int r = 0; r < 8; r++) {
                float2 f = __half22float2(smrows[(size_t)r * 2048 + j2]);
                float ur = su[r];
                sa[kk*2]     += f.x * ur;
                sa[kk*2 + 1] += f.y * ur;
            }
        }
        __syncthreads();
    }
#pragma unroll
    for (int kk = 0; kk < 8; kk++) {
        int j = (t + kk * 256) * 2;
        atomicAdd(&g_s[j], sa[kk*2]);
        atomicAdd(&g_s[j + 1], sa[kk*2 + 1]);
    }
    gbar();
    // sinv tail: block b handles 32 entries
    if (t < 32) {
        int j = blockIdx.x * 32 + t;
        g_sinv[j] = 1.0f / __ldcg(&g_s[j]);
    }
}

// ======================= final P = w_i * P0_ij * sinv_j ; loss partials =======================
__global__ void k_final(float* __restrict__ Pout) {
    int i = blockIdx.x, t = threadIdx.x;
    float wi = g_w[i];
    const __half2* row = (const __half2*)(g_P0h + (size_t)i * N);
    const float2* sv2 = (const float2*)g_sinv;
    float ss = 0.f;
#pragma unroll
    for (int k = 0; k < 8; k++) {
        int jp = t + 256 * k;
        float2 f = __half22float2(row[jp]);
        float2 si = sv2[jp];
        float o0 = wi * f.x * si.x;
        float o1 = wi * f.y * si.y;
        size_t base = (size_t)i * N + (size_t)jp * 2;
        __stcs(&Pout[base], o0);
        __stcs(&Pout[base + 1], o1);
        ss += o0*o0 + o1*o1;
        int j = jp * 2;
        if (i == j) atomicAdd(&g_pdiag, o0);
        else if (i == j + 1) atomicAdd(&g_pdiag, o1);
    }
    __shared__ float red[256];
    red[t] = ss; __syncthreads();
    for (int o = 128; o; o >>= 1) { if (t < o) red[t] += red[t + o]; __syncthreads(); }
    if (t == 0) atomicAdd(&g_psum, red[0]);
}

__global__ void k_loss(float* __restrict__ out) {
    out[0] = sqrtf(g_psum - 2.0f * g_pdiag + (float)N);
}

// ======================= launch =======================
extern "C" void kernel_launch(void* const* d_in, const int* in_sizes, int n_in,
                              void* d_out, int out_size) {
    const float* ft = (const float*)d_in[0];
    const float* fs = (const float*)d_in[1];
    float* out  = (float*)d_out;
    float* Pout = out + 1;
    float* Mout = out + 1 + NN;

    cudaFuncSetAttribute(k_gemm_mma, cudaFuncAttributeMaxDynamicSharedMemorySize, GEMM_SMEM);
    cudaFuncSetAttribute(k_sinkall,  cudaFuncAttributeMaxDynamicSharedMemorySize, 81920);

    k_init<<<128, 256>>>();
    k_prep<<<2 * N, 256>>>(ft, fs);
    k_gemm_mma<<<dim3(32, 32), 256, GEMM_SMEM>>>(Mout);
    k_makeP0<<<N, 256>>>(Mout);
    k_sinkall<<<NB, 256, 81920>>>();
    k_final<<<N, 256>>>(Pout);
    k_loss<<<1, 1>>>(out);
}